// round 17
// baseline (speedup 1.0000x reference)
#include <cuda_runtime.h>
#include <cuda_fp16.h>
#include <math.h>
#include <stdint.h>

#define NN 100000
#define NE 1600000
#define FD 128
#define FD4 (FD/4)
#define SCAN_T 1024
#define SCAN_B ((NN + SCAN_T - 1) / SCAN_T)   // 98
#define NTILES ((NN + 63) / 64)               // 1563
#define GRID_P (148 * 4)                      // persistent blocks, 4/SM

// fp16 smem strides (in halves): pad so MMA fragment loads are conflict-free
#define SH_STR 136                    // 272 B per row; word idx = 4g+t unique
#define SMEM_BYTES ((128*SH_STR + 64*SH_STR) * 2)   // 52,224 B
#define ICHUNK 128   // staged indices per warp per chunk
#define W_U4 ((128 * SH_STR * 2) / 16)   // 2176 uint4 per staged W

// ---------------- static device scratch ----------------
__device__ __half g_hh0[(size_t)NN * FD];   // fp16 activations (ping)
__device__ __half g_hh1[(size_t)NN * FD];   // fp16 activations (pong)
__device__ __half g_wh[4][128 * SH_STR];    // preconverted transposed fp16 W
__device__ int   g_cnt_src[NN];
__device__ int   g_cnt_dst[NN];
__device__ float g_norm_src[NN];
__device__ float g_norm_dst[NN];
__device__ int   g_rowstart[NN];
__device__ int   g_fill[NN];
__device__ int   g_total;
__device__ int   g_tile_ctr[4];             // per-layer tile claim counters
__device__ int   g_csr_src[NE];

// ---------------- setup kernels ----------------
// 4 edges per thread via int4
__global__ void count_deg_kernel(const int* __restrict__ src,
                                 const int* __restrict__ dst) {
    int i = blockIdx.x * blockDim.x + threadIdx.x;
    if (i < NE / 4) {
        int4 s4 = __ldg(&((const int4*)src)[i]);
        int4 d4 = __ldg(&((const int4*)dst)[i]);
        atomicAdd(&g_cnt_src[s4.x], 1); atomicAdd(&g_cnt_dst[d4.x], 1);
        atomicAdd(&g_cnt_src[s4.y], 1); atomicAdd(&g_cnt_dst[d4.y], 1);
        atomicAdd(&g_cnt_src[s4.z], 1); atomicAdd(&g_cnt_dst[d4.z], 1);
        atomicAdd(&g_cnt_src[s4.w], 1); atomicAdd(&g_cnt_dst[d4.w], 1);
    }
}

// single-pass scan: block-local exclusive scan + atomic block base.
// Any block-base order yields a valid CSR (row ranges stay contiguous within a
// scan block, and 64-row tiles never span a 1024-node scan block). Also norms.
__global__ void __launch_bounds__(SCAN_T) scan_fused_kernel() {
    __shared__ int s[SCAN_T];
    __shared__ int base_sh;
    int t = threadIdx.x;
    int i = blockIdx.x * SCAN_T + t;
    int v = (i < NN) ? g_cnt_dst[i] : 0;
    s[t] = v;
    __syncthreads();
    #pragma unroll
    for (int off = 1; off < SCAN_T; off <<= 1) {
        int x = (t >= off) ? s[t - off] : 0;
        __syncthreads();
        s[t] += x;
        __syncthreads();
    }
    if (t == SCAN_T - 1) base_sh = atomicAdd(&g_total, s[t]);
    __syncthreads();
    if (i < NN) {
        int rs = base_sh + s[t] - v;
        g_rowstart[i] = rs;
        g_fill[i] = rs;
        g_norm_src[i] = rsqrtf(fmaxf((float)g_cnt_src[i], 1.0f));
        g_norm_dst[i] = rsqrtf(fmaxf((float)g_cnt_dst[i], 1.0f));
    }
}

// 4 edges per thread via int4
__global__ void fill_csr_kernel(const int* __restrict__ src,
                                const int* __restrict__ dst) {
    int i = blockIdx.x * blockDim.x + threadIdx.x;
    if (i < NE / 4) {
        int4 s4 = __ldg(&((const int4*)src)[i]);
        int4 d4 = __ldg(&((const int4*)dst)[i]);
        g_csr_src[atomicAdd(&g_fill[d4.x], 1)] = s4.x;
        g_csr_src[atomicAdd(&g_fill[d4.y], 1)] = s4.y;
        g_csr_src[atomicAdd(&g_fill[d4.z], 1)] = s4.z;
        g_csr_src[atomicAdd(&g_fill[d4.w], 1)] = s4.w;
    }
}

// convert x*norm_src -> fp16
__global__ void convert_x_kernel(const float* __restrict__ x, __half* __restrict__ o) {
    int i = blockIdx.x * blockDim.x + threadIdx.x;
    if (i < NN * FD4) {
        int row = i >> 5;
        float ns = __ldg(&g_norm_src[row]);
        float4 v = __ldg(&((const float4*)x)[i]);
        __half2 a = __floats2half2_rn(v.x * ns, v.y * ns);
        __half2 b = __floats2half2_rn(v.z * ns, v.w * ns);
        uint2 packed;
        packed.x = *(uint32_t*)&a;
        packed.y = *(uint32_t*)&b;
        ((uint2*)o)[i] = packed;
    }
}

// pre-convert all 4 W [k][n] fp32 -> transposed padded fp16 [n][SH_STR k]
__global__ void convert_w_all_kernel(const float* __restrict__ W0,
                                     const float* __restrict__ W1,
                                     const float* __restrict__ W2,
                                     const float* __restrict__ W3,
                                     __half* __restrict__ o) {
    int idx = blockIdx.x * blockDim.x + threadIdx.x;
    if (idx < 4 * FD * FD) {
        int L = idx >> 14;
        int r = idx & (FD * FD - 1);
        int n = r >> 7;
        int k = r & 127;
        const float* W = (L == 0) ? W0 : (L == 1) ? W1 : (L == 2) ? W2 : W3;
        o[(size_t)L * 128 * SH_STR + n * SH_STR + k] =
            __float2half_rn(__ldg(&W[k * FD + n]));
    }
}

// ---------------- helpers ----------------
__device__ __forceinline__ void mma_f16(float* c,
    uint32_t a0, uint32_t a1, uint32_t a2, uint32_t a3,
    uint32_t b0, uint32_t b1)
{
    asm volatile(
        "mma.sync.aligned.m16n8k16.row.col.f32.f16.f16.f32 "
        "{%0,%1,%2,%3}, {%4,%5,%6,%7}, {%8,%9}, {%0,%1,%2,%3};"
        : "+f"(c[0]), "+f"(c[1]), "+f"(c[2]), "+f"(c[3])
        : "r"(a0), "r"(a1), "r"(a2), "r"(a3), "r"(b0), "r"(b1));
}

__device__ __forceinline__ float gelu_exact(float x) {
    return 0.5f * x * (1.0f + erff(x * 0.7071067811865476f));
}

__device__ __forceinline__ void acc_h4(float4& acc, uint2 raw) {
    __half2 ha = *(__half2*)&raw.x;
    __half2 hb = *(__half2*)&raw.y;
    float2 fa = __half22float2(ha);
    float2 fb = __half22float2(hb);
    acc.x += fa.x; acc.y += fa.y; acc.z += fb.x; acc.w += fb.y;
}

// flush fp32 accumulator to fp16 sA row (4 halves per lane)
__device__ __forceinline__ void flush_row(__half* sA, int row, int lane, float4 acc) {
    __half2 a = __floats2half2_rn(acc.x, acc.y);
    __half2 b = __floats2half2_rn(acc.z, acc.w);
    uint2 p;
    p.x = *(uint32_t*)&a;
    p.y = *(uint32_t*)&b;
    *(uint2*)(sA + row * SH_STR + lane * 4) = p;
}

// gather a 4-row slot (rows [r0glob, r0glob+4)) into sA rows [sArow0, +4).
// Rows within a tile are contiguous in the CSR; boundaries from 5 direct loads.
__device__ __forceinline__ void gather_slot(
    const uint2* __restrict__ hp, int r0glob, int lane,
    __half* __restrict__ sA, int sArow0, int* __restrict__ myIdx)
{
    int bnd[5];
    bnd[0] = (r0glob < NN) ? __ldg(&g_rowstart[r0glob]) : 0;
    int run = bnd[0];
    #pragma unroll
    for (int i = 0; i < 4; ++i) {
        int rr = r0glob + i;
        int c = (rr < NN) ? __ldg(&g_cnt_dst[rr]) : 0;
        run += c;
        bnd[i + 1] = run;
    }
    int beg = bnd[0], end = bnd[4];
    int cur = 0;
    int next = bnd[1];
    float4 acc = make_float4(0.f, 0.f, 0.f, 0.f);

    #pragma unroll 1
    for (int cs = beg; cs < end; cs += ICHUNK) {
        int cnt = end - cs;
        if (cnt > ICHUNK) cnt = ICHUNK;
        #pragma unroll
        for (int i = 0; i < 4; ++i) {
            int j = lane + 32 * i;
            if (j < cnt) myIdx[j] = __ldg(&g_csr_src[cs + j]);
        }
        __syncwarp();

        int j = 0;
        uint2 v[8];
        bool pro = (cnt >= 8);
        if (pro) {
            #pragma unroll
            for (int q = 0; q < 8; ++q) {
                int s = myIdx[q];
                v[q] = __ldg(&hp[s * 32 + lane]);
            }
        }
        #pragma unroll 1
        for (; j + 16 <= cnt; j += 8) {
            uint2 w[8];
            #pragma unroll
            for (int q = 0; q < 8; ++q) {
                int s = myIdx[j + 8 + q];
                w[q] = __ldg(&hp[s * 32 + lane]);
            }
            #pragma unroll
            for (int q = 0; q < 8; ++q) {
                int ee = cs + j + q;
                while (ee >= next) {                 // warp-uniform
                    flush_row(sA, sArow0 + cur, lane, acc);
                    acc = make_float4(0.f, 0.f, 0.f, 0.f);
                    ++cur;
                    next = bnd[cur + 1];
                }
                acc_h4(acc, v[q]);
            }
            #pragma unroll
            for (int q = 0; q < 8; ++q) v[q] = w[q];
        }
        if (pro) {
            #pragma unroll
            for (int q = 0; q < 8; ++q) {
                int ee = cs + j + q;
                while (ee >= next) {
                    flush_row(sA, sArow0 + cur, lane, acc);
                    acc = make_float4(0.f, 0.f, 0.f, 0.f);
                    ++cur;
                    next = bnd[cur + 1];
                }
                acc_h4(acc, v[q]);
            }
            j += 8;
        }
        {   // remainder (< 8 edges)
            uint2 rv[8]; int have = cnt - j;
            #pragma unroll
            for (int q = 0; q < 8; ++q) {
                if (q < have) {
                    int s = myIdx[j + q];
                    rv[q] = __ldg(&hp[s * 32 + lane]);
                }
            }
            #pragma unroll
            for (int q = 0; q < 8; ++q) {
                if (q < have) {
                    int ee = cs + j + q;
                    while (ee >= next) {
                        flush_row(sA, sArow0 + cur, lane, acc);
                        acc = make_float4(0.f, 0.f, 0.f, 0.f);
                        ++cur;
                        next = bnd[cur + 1];
                    }
                    acc_h4(acc, rv[q]);
                }
            }
        }
        __syncwarp();   // protect myIdx before next chunk overwrites
    }
    // flush current row and zero-fill remaining rows
    #pragma unroll
    for (int rr = 0; rr < 4; ++rr) {
        if (rr >= cur) {
            flush_row(sA, sArow0 + rr, lane, acc);
            acc = make_float4(0.f, 0.f, 0.f, 0.f);
        }
    }
}

// ---------------- persistent fused gather + fp16 MMA + epilogue ----------------
// Fixed grid of 592 blocks (4/SM). Each block stages W once, then claims
// 64-row tiles from a per-layer global counter. Per tile: block-local
// work stealing over 16 slots x 4 rows, fp16 m16n8k16 GEMM, fused epilogue.
template <bool GELU, bool PRESCALE, bool LNORM>
__global__ void __launch_bounds__(256, 4) gcn_fused_kernel(
    const __half* __restrict__ hin,   // [NN, FD] fp16, already *norm_src
    const __half* __restrict__ Wh,    // [128][SH_STR] transposed fp16 W
    const float* __restrict__ bias,   // [FD]
    __half* __restrict__ outh,        // fp16 out (L1-L3)
    float* __restrict__ outf,         // fp32 out (L4)
    const float* __restrict__ gamma,
    const float* __restrict__ beta,
    int layer)
{
    extern __shared__ __half smh[];
    __half* sWt = smh;                    // [128 n][SH_STR k] transposed W
    __half* sA  = smh + 128 * SH_STR;     // [64 row][SH_STR k]
    __shared__ int sIdx[8][ICHUNK];       // staged edge indices (per warp)
    __shared__ int sSlot;                 // work-stealing slot counter
    __shared__ int sTile;                 // claimed tile
    int tid  = threadIdx.x;
    int warp = tid >> 5;
    int lane = tid & 31;

    // stage W once: straight uint4 copy of preconverted layout
    {
        const uint4* Wg = (const uint4*)Wh;
        uint4* sW4 = (uint4*)sWt;
        #pragma unroll
        for (int i = 0; i < 9; ++i) {
            int idx = tid + i * 256;
            if (idx < W_U4) sW4[idx] = __ldg(&Wg[idx]);
        }
    }

    const uint2* hp = (const uint2*)hin;  // row = 32 uint2 (256 B)
    int g = lane >> 2;        // 0..7
    int t = lane & 3;         // 0..3
    int rtbase = (warp & 3) * 16;
    int chbase = (warp >> 2) * 64;

    #pragma unroll 1
    for (;;) {
        // claim next tile (also resets slot counter); barrier publishes both
        if (tid == 0) {
            sTile = atomicAdd(&g_tile_ctr[layer], 1);
            sSlot = 0;
        }
        __syncthreads();
        int tile = sTile;
        if (tile >= NTILES) break;
        int rowbase = tile * 64;

        // ---- gather via block-local work stealing over 16 slots x 4 rows ----
        for (;;) {
            int s;
            if (lane == 0) s = atomicAdd(&sSlot, 1);
            s = __shfl_sync(0xFFFFFFFFu, s, 0);
            if (s >= 16) break;
            gather_slot(hp, rowbase + 4 * s, lane, sA, 4 * s, sIdx[warp]);
        }
        __syncthreads();

        // ---- fp16 tensor-core GEMM: D[64x128] = sA @ W ----
        float c[8][4];
        #pragma unroll
        for (int n = 0; n < 8; ++n)
            #pragma unroll
            for (int j = 0; j < 4; ++j) c[n][j] = 0.f;

        const __half* sAr0 = sA + (rtbase + g) * SH_STR;
        const __half* sAr1 = sA + (rtbase + g + 8) * SH_STR;
        #pragma unroll
        for (int k = 0; k < 8; ++k) {
            int k0 = k * 16;
            uint32_t a0 = *(const uint32_t*)(sAr0 + k0 + t * 2);
            uint32_t a1 = *(const uint32_t*)(sAr1 + k0 + t * 2);
            uint32_t a2 = *(const uint32_t*)(sAr0 + k0 + 8 + t * 2);
            uint32_t a3 = *(const uint32_t*)(sAr1 + k0 + 8 + t * 2);
            #pragma unroll
            for (int n = 0; n < 8; ++n) {
                int ncol = chbase + n * 8 + g;
                uint32_t b0 = *(const uint32_t*)(sWt + ncol * SH_STR + k0 + t * 2);
                uint32_t b1 = *(const uint32_t*)(sWt + ncol * SH_STR + k0 + 8 + t * 2);
                mma_f16(c[n], a0, a1, a2, a3, b0, b1);
            }
        }

        // ---- epilogue ----
        int row0 = rowbase + rtbase + g;
        int row1 = row0 + 8;
        float nd0 = 0.f, nd1 = 0.f, ns0 = 1.f, ns1 = 1.f;
        if (row0 < NN) { nd0 = __ldg(&g_norm_dst[row0]); if (PRESCALE) ns0 = __ldg(&g_norm_src[row0]); }
        if (row1 < NN) { nd1 = __ldg(&g_norm_dst[row1]); if (PRESCALE) ns1 = __ldg(&g_norm_src[row1]); }

        if (!LNORM) {
            #pragma unroll
            for (int n = 0; n < 8; ++n) {
                int col = chbase + n * 8 + t * 2;
                float2 bv = *(const float2*)(bias + col);
                if (row0 < NN) {
                    float ox = c[n][0] * nd0 + bv.x;
                    float oy = c[n][1] * nd0 + bv.y;
                    if (GELU) { ox = gelu_exact(ox); oy = gelu_exact(oy); }
                    if (PRESCALE) { ox *= ns0; oy *= ns0; }
                    ((__half2*)outh)[row0 * 64 + (col >> 1)] = __floats2half2_rn(ox, oy);
                }
                if (row1 < NN) {
                    float ox = c[n][2] * nd1 + bv.x;
                    float oy = c[n][3] * nd1 + bv.y;
                    if (GELU) { ox = gelu_exact(ox); oy = gelu_exact(oy); }
                    if (PRESCALE) { ox *= ns1; oy *= ns1; }
                    ((__half2*)outh)[row1 * 64 + (col >> 1)] = __floats2half2_rn(ox, oy);
                }
            }
        } else {
            float s0 = 0.f, q0 = 0.f, s1 = 0.f, q1 = 0.f;
            #pragma unroll
            for (int n = 0; n < 8; ++n) {
                int col = chbase + n * 8 + t * 2;
                float2 bv = *(const float2*)(bias + col);
                float h00 = c[n][0] * nd0 + bv.x;
                float h01 = c[n][1] * nd0 + bv.y;
                float h10 = c[n][2] * nd1 + bv.x;
                float h11 = c[n][3] * nd1 + bv.y;
                c[n][0] = h00; c[n][1] = h01; c[n][2] = h10; c[n][3] = h11;
                s0 += h00 + h01; q0 += h00 * h00 + h01 * h01;
                s1 += h10 + h11; q1 += h10 * h10 + h11 * h11;
            }
            __syncthreads();                 // sA GEMM reads done; reuse as LN scratch
            float2* sLN = (float2*)sA;       // [64][8] overlay
            int slot = (warp >> 2) * 4 + t;
            sLN[(rtbase + g) * 8 + slot]     = make_float2(s0, q0);
            sLN[(rtbase + g + 8) * 8 + slot] = make_float2(s1, q1);
            __syncthreads();
            float ts0 = 0.f, tq0 = 0.f, ts1 = 0.f, tq1 = 0.f;
            #pragma unroll
            for (int k = 0; k < 8; ++k) {
                float2 p0 = sLN[(rtbase + g) * 8 + k];
                float2 p1 = sLN[(rtbase + g + 8) * 8 + k];
                ts0 += p0.x; tq0 += p0.y;
                ts1 += p1.x; tq1 += p1.y;
            }
            float mu0 = ts0 * (1.0f / FD);
            float mu1 = ts1 * (1.0f / FD);
            float inv0 = rsqrtf(fmaxf(tq0 * (1.0f / FD) - mu0 * mu0, 0.f) + 1e-5f);
            float inv1 = rsqrtf(fmaxf(tq1 * (1.0f / FD) - mu1 * mu1, 0.f) + 1e-5f);
            #pragma unroll
            for (int n = 0; n < 8; ++n) {
                int col = chbase + n * 8 + t * 2;
                float2 gv = *(const float2*)(gamma + col);
                float2 bt = *(const float2*)(beta + col);
                if (row0 < NN) {
                    float ox = (c[n][0] - mu0) * inv0 * gv.x + bt.x;
                    float oy = (c[n][1] - mu0) * inv0 * gv.y + bt.y;
                    *(float2*)(outf + (size_t)row0 * FD + col) = make_float2(ox, oy);
                }
                if (row1 < NN) {
                    float ox = (c[n][2] - mu1) * inv1 * gv.x + bt.x;
                    float oy = (c[n][3] - mu1) * inv1 * gv.y + bt.y;
                    *(float2*)(outf + (size_t)row1 * FD + col) = make_float2(ox, oy);
                }
            }
        }
        __syncthreads();   // all sA reads done before next tile's gather
    }
}

// ---------------- launch ----------------
extern "C" void kernel_launch(void* const* d_in, const int* in_sizes, int n_in,
                              void* d_out, int out_size)
{
    const float* x     = (const float*)d_in[0];
    const int*   src   = (const int*)  d_in[1];
    const int*   dst   = (const int*)  d_in[2];
    const float* Ws[4] = { (const float*)d_in[3], (const float*)d_in[5],
                           (const float*)d_in[7], (const float*)d_in[9] };
    const float* bs[4] = { (const float*)d_in[4], (const float*)d_in[6],
                           (const float*)d_in[8], (const float*)d_in[10] };
    const float* gamma = (const float*)d_in[11];
    const float* beta  = (const float*)d_in[12];
    float* out = (float*)d_out;

    __half *h0, *h1, *wh;
    int *cnt_src_p, *cnt_dst_p, *total_p, *tile_ctr_p;
    cudaGetSymbolAddress((void**)&h0, g_hh0);
    cudaGetSymbolAddress((void**)&h1, g_hh1);
    cudaGetSymbolAddress((void**)&wh, g_wh);
    cudaGetSymbolAddress((void**)&cnt_src_p, g_cnt_src);
    cudaGetSymbolAddress((void**)&cnt_dst_p, g_cnt_dst);
    cudaGetSymbolAddress((void**)&total_p, g_total);
    cudaGetSymbolAddress((void**)&tile_ctr_p, g_tile_ctr);

    cudaFuncSetAttribute(gcn_fused_kernel<true, true, false>,
                         cudaFuncAttributeMaxDynamicSharedMemorySize, SMEM_BYTES);
    cudaFuncSetAttribute(gcn_fused_kernel<false, false, true>,
                         cudaFuncAttributeMaxDynamicSharedMemorySize, SMEM_BYTES);

    const int T = 256;
    cudaMemsetAsync(cnt_src_p, 0, NN * sizeof(int));
    cudaMemsetAsync(cnt_dst_p, 0, NN * sizeof(int));
    cudaMemsetAsync(total_p, 0, sizeof(int));
    cudaMemsetAsync(tile_ctr_p, 0, 4 * sizeof(int));
    count_deg_kernel<<<(NE / 4 + T - 1) / T, T>>>(src, dst);
    scan_fused_kernel<<<SCAN_B, SCAN_T>>>();     // scan + fill + norms
    fill_csr_kernel<<<(NE / 4 + T - 1) / T, T>>>(src, dst);

    // preconvert all weights (one launch) + x*norm_src -> fp16 h0
    convert_w_all_kernel<<<(4 * FD * FD + T - 1) / T, T>>>(
        Ws[0], Ws[1], Ws[2], Ws[3], wh);
    convert_x_kernel<<<(NN * FD4 + T - 1) / T, T>>>(x, h0);

    gcn_fused_kernel<true, true, false><<<GRID_P, T, SMEM_BYTES>>>(
        h0, wh + 0 * 128 * SH_STR, bs[0], h1, nullptr, nullptr, nullptr, 0);
    gcn_fused_kernel<true, true, false><<<GRID_P, T, SMEM_BYTES>>>(
        h1, wh + 1 * 128 * SH_STR, bs[1], h0, nullptr, nullptr, nullptr, 1);
    gcn_fused_kernel<true, true, false><<<GRID_P, T, SMEM_BYTES>>>(
        h0, wh + 2 * 128 * SH_STR, bs[2], h1, nullptr, nullptr, nullptr, 2);
    gcn_fused_kernel<false, false, true><<<GRID_P, T, SMEM_BYTES>>>(
        h1, wh + 3 * 128 * SH_STR, bs[3], nullptr, out, gamma, beta, 3);
}